// round 1
// baseline (speedup 1.0000x reference)
#include <cuda_runtime.h>
#include <cuda_bf16.h>
#include <math.h>

#define GRID_H   48
#define NPTS     2304      // 48*48
#define NCH      16
#define NBATCH   2
#define NKNOT    16
#define WIN      19        // 2*9+1 candidate window
#define WIN2     361
#define WARPS_PB 8         // i's per block
#define ROUNDS   12        // ceil(361/32)

__global__ __launch_bounds__(256, 2)
void si_blocks_kernel(const float* __restrict__ x,
                      const float* __restrict__ phi_w1, const float* __restrict__ phi_b1,
                      const float* __restrict__ phi_w2, const float* __restrict__ phi_b2,
                      const float* __restrict__ h_w1,  const float* __restrict__ h_b1,
                      const float* __restrict__ h_w2,  const float* __restrict__ h_b2,
                      const float* __restrict__ S_m,
                      float* __restrict__ out)
{
    __shared__ float  sW2[32], sW3[32], sV[32], sS[NKNOT];
    __shared__ float  sB2;
    __shared__ float  sA[WARPS_PB][32];
    __shared__ float2 sWJ[WARPS_PB][WIN2];   // (weight, j*16 as int bits)

    const int tid  = threadIdx.x;
    const int warp = tid >> 5;
    const int lane = tid & 31;

    // Block-shared small tensors
    if (tid < 32) {
        sW2[tid] = phi_w1[64 + tid];   // W1 row 2 (xj)
        sW3[tid] = phi_w1[96 + tid];   // W1 row 3 (yj)
        sV [tid] = phi_w2[tid];        // (32,1)
    } else if (tid < 48) {
        sS[tid - 32] = S_m[tid - 32];
    }
    if (tid == 48) sB2 = phi_b2[0];

    const int   i   = blockIdx.x * WARPS_PB + warp;
    const int   ri  = i / GRID_H;
    const int   ci  = i - ri * GRID_H;
    const float inv47 = 1.0f / 47.0f;
    const float xi = (float)ri * inv47;
    const float yi = (float)ci * inv47;

    // ---- h_net: per-i bandwidth (lane k = hidden unit k, warp reduce) ----
    float hz = fmaxf(fmaf(xi, h_w1[lane], fmaf(yi, h_w1[32 + lane], h_b1[lane])), 0.0f)
               * h_w2[lane];
    #pragma unroll
    for (int o = 16; o; o >>= 1) hz += __shfl_xor_sync(0xffffffffu, hz, o);
    hz += h_b2[0];
    const float hval  = fmaxf(hz, 0.0f) + log1pf(expf(-fabsf(hz)));   // softplus
    const float inv_h = 1.0f / (hval + 1e-6f);

    // ---- per-i part of phi pre-activation: a_i[k] ----
    sA[warp][lane] = fmaf(xi, phi_w1[lane], fmaf(yi, phi_w1[32 + lane], phi_b1[lane]));
    __syncthreads();

    // ---- Phase A: candidate window sweep ----
    float xjv[ROUNDS], yjv[ROUNDS], pacc[ROUNDS];
    #pragma unroll
    for (int r = 0; r < ROUNDS; r++) {
        int cand = lane + r * 32;
        int dr = cand / WIN - 9;
        int dc = cand - (cand / WIN) * WIN - 9;
        xjv[r]  = (float)(ri + dr) * inv47;
        yjv[r]  = (float)(ci + dc) * inv47;
        pacc[r] = 0.0f;
    }
    // phi hidden layer: outer k, inner candidates (hoisted scalar loads)
    #pragma unroll
    for (int k = 0; k < 32; k++) {
        const float a  = sA[warp][k];
        const float w2 = sW2[k];
        const float w3 = sW3[k];
        const float v  = sV[k];
        #pragma unroll
        for (int r = 0; r < ROUNDS; r++) {
            float t = fmaf(yjv[r], w3, fmaf(xjv[r], w2, a));
            pacc[r] = fmaf(v, fmaxf(t, 0.0f), pacc[r]);
        }
    }

    // spline + mask + compaction into shared
    int cnt = 0;
    #pragma unroll
    for (int r = 0; r < ROUNDS; r++) {
        int  cand = lane + r * 32;
        int  q    = cand / WIN;
        int  dr   = q - 9;
        int  dc   = cand - q * WIN - 9;
        int  rj   = ri + dr;
        int  cj   = ci + dc;
        float d2  = (float)(dr * dr + dc * dc) * (inv47 * inv47);
        bool ok   = (cand < WIN2) && (rj >= 0) && (rj < GRID_H) &&
                    (cj >= 0) && (cj < GRID_H) && (d2 <= 0.04f);  // RADIUS^2, wide margin
        unsigned m = __ballot_sync(0xffffffffu, ok);
        if (ok) {
            float dist = sqrtf(d2);
            float rr   = fminf(fmaxf(dist * inv_h, 0.0f), 1.0f);
            int   idx  = min(max((int)floorf(rr * 15.0f), 0), 14);
            float tk   = (float)idx * (1.0f / 15.0f);
            float tk1  = (float)(idx + 1) * (1.0f / 15.0f);
            float wr   = (rr - tk) / (tk1 - tk + 1e-8f);
            float psi  = (1.0f - wr) * sS[idx] + wr * sS[idx + 1];
            float phi  = pacc[r] + sB2;
            float w    = phi * psi;
            int  pos   = cnt + __popc(m & ((1u << lane) - 1u));
            sWJ[warp][pos] = make_float2(w, __int_as_float((rj * GRID_H + cj) * NCH));
        }
        cnt += __popc(m);
    }
    __syncwarp();

    // ---- Phase B: lanes = (b,c) pairs; one coalesced 128B LDG per neighbor ----
    const int b = lane >> 4;
    const int c = lane & 15;
    const float* xp = x + b * (NPTS * NCH) + c;
    float acc = 0.0f;
    #pragma unroll 4
    for (int t = 0; t < cnt; t++) {
        float2 wj = sWJ[warp][t];
        acc = fmaf(wj.x, __ldg(xp + __float_as_int(wj.y)), acc);
    }
    out[b * (NPTS * NCH) + i * NCH + c] = acc * (1.0f / (float)cnt);
}

extern "C" void kernel_launch(void* const* d_in, const int* in_sizes, int n_in,
                              void* d_out, int out_size)
{
    const float* x      = (const float*)d_in[0];
    const float* phi_w1 = (const float*)d_in[1];
    const float* phi_b1 = (const float*)d_in[2];
    const float* phi_w2 = (const float*)d_in[3];
    const float* phi_b2 = (const float*)d_in[4];
    const float* h_w1   = (const float*)d_in[5];
    const float* h_b1   = (const float*)d_in[6];
    const float* h_w2   = (const float*)d_in[7];
    const float* h_w2b  = (const float*)d_in[8];
    const float* S_m    = (const float*)d_in[9];
    float* out = (float*)d_out;

    si_blocks_kernel<<<NPTS / WARPS_PB, 256>>>(
        x, phi_w1, phi_b1, phi_w2, phi_b2,
        h_w1, h_b1, h_w2, h_w2b, S_m, out);
}

// round 2
// speedup vs baseline: 1.2912x; 1.2912x over previous
#include <cuda_runtime.h>
#include <cuda_bf16.h>
#include <math.h>

#define GRID_H   48
#define NPTS     2304      // 48*48
#define NCH      16
#define NKNOT    16
#define WIN      19        // 2*9+1 candidate window
#define WIN2     361
#define IPB      4         // i's per block (each i = 2 warps)
#define RPW      6         // rounds per warp (covers lane + 32*(2r+sub), up to 383)

__global__ __launch_bounds__(256, 4)
void si_blocks_kernel(const float* __restrict__ x,
                      const float* __restrict__ phi_w1, const float* __restrict__ phi_b1,
                      const float* __restrict__ phi_w2, const float* __restrict__ phi_b2,
                      const float* __restrict__ h_w1,  const float* __restrict__ h_b1,
                      const float* __restrict__ h_w2,  const float* __restrict__ h_b2,
                      const float* __restrict__ S_m,
                      float* __restrict__ out)
{
    __shared__ float  sW2[32], sW3[32], sV[32], sS[NKNOT];
    __shared__ float  sB2;
    __shared__ float  sA[IPB][32];
    __shared__ float2 sWJ[IPB][2][RPW * 32];   // (weight, j*16 as int bits)
    __shared__ int    sCnt[IPB][2];
    __shared__ float  sPart[IPB][32];

    const int tid  = threadIdx.x;
    const int warp = tid >> 5;
    const int lane = tid & 31;
    const int p    = warp >> 1;   // which i within block
    const int sub  = warp & 1;    // which half-warp-pair

    // Block-shared small tensors
    if (tid < 32) {
        sW2[tid] = phi_w1[64 + tid];   // W1 row 2 (xj)
        sW3[tid] = phi_w1[96 + tid];   // W1 row 3 (yj)
        sV [tid] = phi_w2[tid];        // (32,1)
    } else if (tid < 48) {
        sS[tid - 32] = S_m[tid - 32];
    }
    if (tid == 48) sB2 = phi_b2[0];

    const int   i   = blockIdx.x * IPB + p;
    const int   ri  = i / GRID_H;
    const int   ci  = i - ri * GRID_H;
    const float inv47 = 1.0f / 47.0f;
    const float xi = (float)ri * inv47;
    const float yi = (float)ci * inv47;

    // ---- h_net: per-i bandwidth (lane k = hidden unit k, warp reduce) ----
    float hz = fmaxf(fmaf(xi, h_w1[lane], fmaf(yi, h_w1[32 + lane], h_b1[lane])), 0.0f)
               * h_w2[lane];
    #pragma unroll
    for (int o = 16; o; o >>= 1) hz += __shfl_xor_sync(0xffffffffu, hz, o);
    hz += h_b2[0];
    const float hval  = fmaxf(hz, 0.0f) + log1pf(expf(-fabsf(hz)));   // softplus
    const float inv_h = 1.0f / (hval + 1e-6f);

    // ---- per-i part of phi pre-activation: a_i[k] (one warp of the pair) ----
    if (sub == 0)
        sA[p][lane] = fmaf(xi, phi_w1[lane], fmaf(yi, phi_w1[32 + lane], phi_b1[lane]));
    __syncthreads();

    // ---- Phase A: this warp's interleaved candidate rounds ----
    float xjv[RPW], yjv[RPW], pacc[RPW];
    #pragma unroll
    for (int r = 0; r < RPW; r++) {
        int cand = lane + 32 * (2 * r + sub);
        int q  = cand / WIN;
        int dr = q - 9;
        int dc = cand - q * WIN - 9;
        xjv[r]  = (float)(ri + dr) * inv47;
        yjv[r]  = (float)(ci + dc) * inv47;
        pacc[r] = 0.0f;
    }
    // phi hidden layer: outer k, inner candidates
    #pragma unroll
    for (int k = 0; k < 32; k++) {
        const float a  = sA[p][k];
        const float w2 = sW2[k];
        const float w3 = sW3[k];
        const float v  = sV[k];
        #pragma unroll
        for (int r = 0; r < RPW; r++) {
            float t = fmaf(yjv[r], w3, fmaf(xjv[r], w2, a));
            pacc[r] = fmaf(v, fmaxf(t, 0.0f), pacc[r]);
        }
    }

    // spline + mask + compaction into this warp's shared segment
    int cnt = 0;
    #pragma unroll
    for (int r = 0; r < RPW; r++) {
        int  cand = lane + 32 * (2 * r + sub);
        int  q    = cand / WIN;
        int  dr   = q - 9;
        int  dc   = cand - q * WIN - 9;
        int  rj   = ri + dr;
        int  cj   = ci + dc;
        int  id2  = dr * dr + dc * dc;
        bool ok   = (cand < WIN2) && (rj >= 0) && (rj < GRID_H) &&
                    (cj >= 0) && (cj < GRID_H) && (id2 <= 88);  // (0.2*47)^2 = 88.36
        unsigned m = __ballot_sync(0xffffffffu, ok);
        if (ok) {
            float dist = sqrtf((float)id2) * inv47;
            float rr   = fminf(fmaxf(dist * inv_h, 0.0f), 1.0f);
            int   idx  = min(max((int)floorf(rr * 15.0f), 0), 14);
            float tk   = (float)idx * (1.0f / 15.0f);
            float tk1  = (float)(idx + 1) * (1.0f / 15.0f);
            float wr   = (rr - tk) / (tk1 - tk + 1e-8f);
            float psi  = (1.0f - wr) * sS[idx] + wr * sS[idx + 1];
            float phi  = pacc[r] + sB2;
            float w    = phi * psi;
            int  pos   = cnt + __popc(m & ((1u << lane) - 1u));
            sWJ[p][sub][pos] = make_float2(w, __int_as_float((rj * GRID_H + cj) * NCH));
        }
        cnt += __popc(m);
    }
    if (lane == 0) sCnt[p][sub] = cnt;
    __syncthreads();

    // ---- Phase B: lanes = (b,c) pairs; each warp does its own list ----
    const int b = lane >> 4;
    const int c = lane & 15;
    const float* xp = x + b * (NPTS * NCH) + c;
    float acc = 0.0f;
    #pragma unroll 4
    for (int t = 0; t < cnt; t++) {
        float2 wj = sWJ[p][sub][t];
        acc = fmaf(wj.x, __ldg(xp + __float_as_int(wj.y)), acc);
    }

    // combine the two warps of the pair
    if (sub == 1) sPart[p][lane] = acc;
    __syncthreads();
    if (sub == 0) {
        acc += sPart[p][lane];
        int tot = sCnt[p][0] + sCnt[p][1];
        out[b * (NPTS * NCH) + i * NCH + c] = acc * (1.0f / (float)tot);
    }
}

extern "C" void kernel_launch(void* const* d_in, const int* in_sizes, int n_in,
                              void* d_out, int out_size)
{
    const float* x      = (const float*)d_in[0];
    const float* phi_w1 = (const float*)d_in[1];
    const float* phi_b1 = (const float*)d_in[2];
    const float* phi_w2 = (const float*)d_in[3];
    const float* phi_b2 = (const float*)d_in[4];
    const float* h_w1   = (const float*)d_in[5];
    const float* h_b1   = (const float*)d_in[6];
    const float* h_w2   = (const float*)d_in[7];
    const float* h_b2   = (const float*)d_in[8];
    const float* S_m    = (const float*)d_in[9];
    float* out = (float*)d_out;

    si_blocks_kernel<<<NPTS / IPB, 256>>>(
        x, phi_w1, phi_b1, phi_w2, phi_b2,
        h_w1, h_b1, h_w2, h_b2, S_m, out);
}

// round 3
// speedup vs baseline: 1.4380x; 1.1138x over previous
#include <cuda_runtime.h>
#include <cuda_bf16.h>
#include <math.h>

#define GRID_H   48
#define NPTS     2304      // 48*48
#define NCH      16
#define WIN      19        // 2*9+1 candidate window
#define WIN2     361
#define IPB      2         // i's per block
#define SUBW     4         // warps per i
#define RPW      3         // rounds per warp: cand = lane + 32*(4r+sub), covers 0..383
#define MAXE     96        // max compacted entries per warp (3 rounds * 32)
#define XSTRIDE  36864     // NPTS*NCH

__global__ __launch_bounds__(256)
void si_blocks_kernel(const float* __restrict__ x,
                      const float* __restrict__ phi_w1, const float* __restrict__ phi_b1,
                      const float* __restrict__ phi_w2, const float* __restrict__ phi_b2,
                      const float* __restrict__ h_w1,  const float* __restrict__ h_b1,
                      const float* __restrict__ h_w2,  const float* __restrict__ h_b2,
                      const float* __restrict__ S_m,
                      float* __restrict__ out)
{
    __shared__ float  sW2[32], sW3[32], sV[32], sS[16];
    __shared__ float  sB2;
    __shared__ float  sA[IPB][32];
    __shared__ float2 sWJ[IPB][SUBW][MAXE];   // (weight, x-float-offset as int bits)
    __shared__ int    sCnt[IPB][SUBW];
    __shared__ float4 sPart[IPB][SUBW][8];

    const int tid  = threadIdx.x;
    const int warp = tid >> 5;
    const int lane = tid & 31;
    const int p    = warp >> 2;   // which i within block
    const int sub  = warp & 3;    // which quarter of the candidate window

    if (tid < 32) {
        sW2[tid] = phi_w1[64 + tid];   // W1 row 2 (xj)
        sW3[tid] = phi_w1[96 + tid];   // W1 row 3 (yj)
        sV [tid] = phi_w2[tid];
    } else if (tid < 48) {
        sS[tid - 32] = S_m[tid - 32];
    }
    if (tid == 48) sB2 = phi_b2[0];

    const int   i   = blockIdx.x * IPB + p;
    const int   ri  = i / GRID_H;
    const int   ci  = i - ri * GRID_H;
    const float inv47 = 1.0f / 47.0f;
    const float xi = (float)ri * inv47;
    const float yi = (float)ci * inv47;

    // ---- h_net: per-i bandwidth (lane k = hidden unit, warp reduce) ----
    float hz = fmaxf(fmaf(xi, h_w1[lane], fmaf(yi, h_w1[32 + lane], h_b1[lane])), 0.0f)
               * h_w2[lane];
    #pragma unroll
    for (int o = 16; o; o >>= 1) hz += __shfl_xor_sync(0xffffffffu, hz, o);
    hz += h_b2[0];
    const float hval  = fmaxf(hz, 0.0f) + log1pf(expf(-fabsf(hz)));   // softplus
    const float inv_h = 1.0f / (hval + 1e-6f);

    // ---- per-i part of phi pre-activation ----
    if (sub == 0)
        sA[p][lane] = fmaf(xi, phi_w1[lane], fmaf(yi, phi_w1[32 + lane], phi_b1[lane]));
    __syncthreads();

    // ---- Phase A: interleaved candidate rounds for this warp ----
    float xjv[RPW], yjv[RPW], pacc[RPW];
    #pragma unroll
    for (int r = 0; r < RPW; r++) {
        int cand = lane + 32 * (4 * r + sub);
        int q  = cand / WIN;
        int dr = q - 9;
        int dc = cand - q * WIN - 9;
        xjv[r]  = (float)(ri + dr) * inv47;
        yjv[r]  = (float)(ci + dc) * inv47;
        pacc[r] = 0.0f;
    }
    #pragma unroll
    for (int k = 0; k < 32; k++) {
        const float a  = sA[p][k];
        const float w2 = sW2[k];
        const float w3 = sW3[k];
        const float v  = sV[k];
        #pragma unroll
        for (int r = 0; r < RPW; r++) {
            float t = fmaf(yjv[r], w3, fmaf(xjv[r], w2, a));
            pacc[r] = fmaf(v, fmaxf(t, 0.0f), pacc[r]);
        }
    }

    // spline + mask + warp compaction
    int cnt = 0;
    #pragma unroll
    for (int r = 0; r < RPW; r++) {
        int  cand = lane + 32 * (4 * r + sub);
        int  q    = cand / WIN;
        int  dr   = q - 9;
        int  dc   = cand - q * WIN - 9;
        int  rj   = ri + dr;
        int  cj   = ci + dc;
        int  id2  = dr * dr + dc * dc;
        bool ok   = (cand < WIN2) && (rj >= 0) && (rj < GRID_H) &&
                    (cj >= 0) && (cj < GRID_H) && (id2 <= 88);  // (0.2*47)^2 = 88.36
        unsigned m = __ballot_sync(0xffffffffu, ok);
        if (ok) {
            float dist = sqrtf((float)id2) * inv47;
            float rr   = fminf(fmaxf(dist * inv_h, 0.0f), 1.0f);
            int   idx  = min(max((int)floorf(rr * 15.0f), 0), 14);
            float tk   = (float)idx * (1.0f / 15.0f);
            float tk1  = (float)(idx + 1) * (1.0f / 15.0f);
            float wr   = (rr - tk) / (tk1 - tk + 1e-8f);
            float psi  = (1.0f - wr) * sS[idx] + wr * sS[idx + 1];
            float w    = (pacc[r] + sB2) * psi;
            int  pos   = cnt + __popc(m & ((1u << lane) - 1u));
            sWJ[p][sub][pos] = make_float2(w, __int_as_float((rj * GRID_H + cj) * NCH));
        }
        cnt += __popc(m);
    }
    // pad to multiple of 4 with zero-weight entries
    const int cnt4 = (cnt + 3) & ~3;
    if (lane < cnt4 - cnt)
        sWJ[p][sub][cnt + lane] = make_float2(0.0f, __int_as_float(0));
    if (lane == 0) sCnt[p][sub] = cnt;
    __syncwarp();

    // ---- Phase B: vectorized. lane = (n2: neighbor slot, b: batch, q: float4 chunk)
    const int n2 = lane >> 3;
    const int b  = (lane >> 2) & 1;
    const int q  = lane & 3;
    const float* xq = x + b * XSTRIDE + q * 4;
    float4 acc = make_float4(0.f, 0.f, 0.f, 0.f);
    #pragma unroll 2
    for (int t = 0; t < cnt4; t += 4) {
        float2 wj = sWJ[p][sub][t + n2];
        const float4 v = *reinterpret_cast<const float4*>(xq + __float_as_int(wj.y));
        acc.x = fmaf(wj.x, v.x, acc.x);
        acc.y = fmaf(wj.x, v.y, acc.y);
        acc.z = fmaf(wj.x, v.z, acc.z);
        acc.w = fmaf(wj.x, v.w, acc.w);
    }
    // butterfly over the 4 neighbor slots
    #pragma unroll
    for (int o = 8; o <= 16; o <<= 1) {
        acc.x += __shfl_xor_sync(0xffffffffu, acc.x, o);
        acc.y += __shfl_xor_sync(0xffffffffu, acc.y, o);
        acc.z += __shfl_xor_sync(0xffffffffu, acc.z, o);
        acc.w += __shfl_xor_sync(0xffffffffu, acc.w, o);
    }
    if (lane < 8) sPart[p][sub][lane] = acc;   // lane = b*4+q
    __syncthreads();

    // ---- combine the 4 sub-warps, normalize, write ----
    if (sub == 0 && lane < 8) {
        float4 s0 = sPart[p][0][lane];
        float4 s1 = sPart[p][1][lane];
        float4 s2 = sPart[p][2][lane];
        float4 s3 = sPart[p][3][lane];
        int tot = sCnt[p][0] + sCnt[p][1] + sCnt[p][2] + sCnt[p][3];
        float sc = 1.0f / (float)tot;
        float4 o;
        o.x = (s0.x + s1.x + s2.x + s3.x) * sc;
        o.y = (s0.y + s1.y + s2.y + s3.y) * sc;
        o.z = (s0.z + s1.z + s2.z + s3.z) * sc;
        o.w = (s0.w + s1.w + s2.w + s3.w) * sc;
        *reinterpret_cast<float4*>(out + b * XSTRIDE + i * NCH + q * 4) = o;
    }
}

extern "C" void kernel_launch(void* const* d_in, const int* in_sizes, int n_in,
                              void* d_out, int out_size)
{
    const float* x      = (const float*)d_in[0];
    const float* phi_w1 = (const float*)d_in[1];
    const float* phi_b1 = (const float*)d_in[2];
    const float* phi_w2 = (const float*)d_in[3];
    const float* phi_b2 = (const float*)d_in[4];
    const float* h_w1   = (const float*)d_in[5];
    const float* h_b1   = (const float*)d_in[6];
    const float* h_w2   = (const float*)d_in[7];
    const float* h_b2   = (const float*)d_in[8];
    const float* S_m    = (const float*)d_in[9];
    float* out = (float*)d_out;

    si_blocks_kernel<<<NPTS / IPB, 256>>>(
        x, phi_w1, phi_b1, phi_w2, phi_b2,
        h_w1, h_b1, h_w2, h_b2, S_m, out);
}

// round 4
// speedup vs baseline: 1.5802x; 1.0989x over previous
#include <cuda_runtime.h>
#include <math.h>

#define GRID_H   48
#define NPTS     2304      // 48*48
#define NCH      16
#define WIN      19        // 2*9+1 candidate window
#define WIN2     361
#define IPB      2         // i's per block
#define SUBW     4         // warps per i
#define RPW      3         // rounds per warp: cand = lane + 32*(4r+sub)
#define MAXE     100       // 96 + 4 pad slots
#define XSTRIDE  36864     // NPTS*NCH
#define NGRP     1152      // NPTS/IPB
#define GRIDN    740       // 148 SMs * 5 resident blocks

// f32x2 helpers (Blackwell packed fp32)
__device__ __forceinline__ unsigned long long pk2(float lo, float hi) {
    unsigned long long r;
    unsigned a = __float_as_uint(lo), b = __float_as_uint(hi);
    asm("mov.b64 %0, {%1, %2};" : "=l"(r) : "r"(a), "r"(b));
    return r;
}
__device__ __forceinline__ void upk2(unsigned long long v, float& lo, float& hi) {
    unsigned a, b;
    asm("mov.b64 {%0, %1}, %2;" : "=r"(a), "=r"(b) : "l"(v));
    lo = __uint_as_float(a); hi = __uint_as_float(b);
}
__device__ __forceinline__ unsigned long long ffma2(unsigned long long a,
                                                    unsigned long long b,
                                                    unsigned long long c) {
    unsigned long long d;
    asm("fma.rn.f32x2 %0, %1, %2, %3;" : "=l"(d) : "l"(a), "l"(b), "l"(c));
    return d;
}

__global__ __launch_bounds__(256, 5)
void si_blocks_kernel(const float* __restrict__ x,
                      const float* __restrict__ phi_w1, const float* __restrict__ phi_b1,
                      const float* __restrict__ phi_w2, const float* __restrict__ phi_b2,
                      const float* __restrict__ h_w1,  const float* __restrict__ h_b1,
                      const float* __restrict__ h_w2,  const float* __restrict__ h_b2,
                      const float* __restrict__ S_m,
                      float* __restrict__ out)
{
    __shared__ float2 sW0p[16], sW1p[16], sB1p[16];   // phi W1 rows 0,1 + b1 (k-pairs)
    __shared__ float2 sW2p[16], sW3p[16], sVp[16];    // phi W1 rows 2,3 + W2
    __shared__ float  sS[16], sDist[89];
    __shared__ float  sB2;
    __shared__ float  sInvH[IPB];
    __shared__ float2 sAp[IPB][16];
    __shared__ float2 sWJ[IPB][SUBW][MAXE];
    __shared__ int    sCnt[IPB][SUBW];
    __shared__ float4 sPart[IPB][SUBW][8];

    const int tid  = threadIdx.x;
    const int warp = tid >> 5;
    const int lane = tid & 31;
    const int p    = warp >> 2;
    const int sub  = warp & 3;
    const float inv47 = 1.0f / 47.0f;

    // ---- one-time block init ----
    if (tid < 16) {
        sW0p[tid] = make_float2(phi_w1[2*tid],      phi_w1[2*tid + 1]);
        sW1p[tid] = make_float2(phi_w1[32 + 2*tid], phi_w1[33 + 2*tid]);
        sW2p[tid] = make_float2(phi_w1[64 + 2*tid], phi_w1[65 + 2*tid]);
        sW3p[tid] = make_float2(phi_w1[96 + 2*tid], phi_w1[97 + 2*tid]);
        sVp [tid] = make_float2(phi_w2[2*tid],      phi_w2[2*tid + 1]);
        sB1p[tid] = make_float2(phi_b1[2*tid],      phi_b1[2*tid + 1]);
        sS  [tid] = S_m[tid];
    }
    if (tid == 16) sB2 = phi_b2[0];
    if (tid < 89) sDist[tid] = sqrtf((float)tid) * inv47;
    __syncthreads();

    // ---- per-warp window geometry, invariant across groups ----
    int   drv[RPW], dcv[RPW];
    float distv[RPW];
    int   okmask = 0;
    #pragma unroll
    for (int r = 0; r < RPW; r++) {
        int cand = lane + 32 * (4 * r + sub);
        int q    = cand / WIN;
        int dr   = q - 9;
        int dc   = cand - q * WIN - 9;
        drv[r] = dr; dcv[r] = dc;
        int id2 = dr * dr + dc * dc;
        if (cand < WIN2 && id2 <= 88) okmask |= (1 << r);   // (0.2*47)^2 = 88.36
        distv[r] = sDist[min(id2, 88)];
    }

    // Phase-B lane mapping (fixed)
    const int n2 = lane >> 3;
    const int bb = (lane >> 2) & 1;
    const int qq = lane & 3;
    const float* xq = x + bb * XSTRIDE + qq * 4;
    const float CKNOT = 1.0f / (1.0f / 15.0f + 1e-8f);

    for (int grp = blockIdx.x; grp < NGRP; grp += GRIDN) {
        const int   i  = grp * IPB + p;
        const int   ri = i / GRID_H;
        const int   ci = i - ri * GRID_H;
        const float xi = (float)ri * inv47;
        const float yi = (float)ci * inv47;

        if (sub == 0 && lane < 16) {
            // per-i phi pre-activation, k-pairs
            float2 w0 = sW0p[lane], w1 = sW1p[lane], b1 = sB1p[lane];
            sAp[p][lane] = make_float2(
                fmaf(xi, w0.x, fmaf(yi, w1.x, b1.x)),
                fmaf(xi, w0.y, fmaf(yi, w1.y, b1.y)));
        }
        if (sub == 1) {
            // h_net bandwidth
            float hz = fmaxf(fmaf(xi, h_w1[lane], fmaf(yi, h_w1[32 + lane], h_b1[lane])), 0.0f)
                       * h_w2[lane];
            #pragma unroll
            for (int o = 16; o; o >>= 1) hz += __shfl_xor_sync(0xffffffffu, hz, o);
            hz += h_b2[0];
            float hval = fmaxf(hz, 0.0f) + log1pf(expf(-fabsf(hz)));
            if (lane == 0) sInvH[p] = 1.0f / (hval + 1e-6f);
        }
        __syncthreads();

        // ---- Phase A: packed phi hidden layer ----
        unsigned long long xs2[RPW], ys2[RPW], acc2[RPW];
        #pragma unroll
        for (int r = 0; r < RPW; r++) {
            float xj = fmaf((float)drv[r], inv47, xi);
            float yj = fmaf((float)dcv[r], inv47, yi);
            xs2[r] = pk2(xj, xj);
            ys2[r] = pk2(yj, yj);
            acc2[r] = 0ULL;
        }
        #pragma unroll
        for (int k2 = 0; k2 < 16; k2++) {
            float2 w2 = sW2p[k2], w3 = sW3p[k2], vv = sVp[k2], aa = sAp[p][k2];
            unsigned long long w2q = pk2(w2.x, w2.y);
            unsigned long long w3q = pk2(w3.x, w3.y);
            unsigned long long vq  = pk2(vv.x, vv.y);
            unsigned long long aq  = pk2(aa.x, aa.y);
            #pragma unroll
            for (int r = 0; r < RPW; r++) {
                unsigned long long t2 = ffma2(xs2[r], w2q, aq);
                t2 = ffma2(ys2[r], w3q, t2);
                float tl, th; upk2(t2, tl, th);
                tl = fmaxf(tl, 0.0f); th = fmaxf(th, 0.0f);
                acc2[r] = ffma2(pk2(tl, th), vq, acc2[r]);
            }
        }

        // ---- spline + mask + warp compaction ----
        const float inv_h = sInvH[p];
        int cnt = 0;
        #pragma unroll
        for (int r = 0; r < RPW; r++) {
            int  rj = ri + drv[r];
            int  cj = ci + dcv[r];
            bool ok = ((okmask >> r) & 1) && (rj >= 0) && (rj < GRID_H) &&
                      (cj >= 0) && (cj < GRID_H);
            unsigned m = __ballot_sync(0xffffffffu, ok);
            if (ok) {
                float rr  = fminf(distv[r] * inv_h, 1.0f);
                int   idx = min((int)(rr * 15.0f), 14);
                float wr  = (rr - (float)idx * (1.0f / 15.0f)) * CKNOT;
                float s0  = sS[idx];
                float psi = fmaf(wr, sS[idx + 1] - s0, s0);
                float al, ah; upk2(acc2[r], al, ah);
                float w   = (al + ah + sB2) * psi;
                int  pos  = cnt + __popc(m & ((1u << lane) - 1u));
                sWJ[p][sub][pos] = make_float2(w, __int_as_float(rj * (GRID_H * NCH) + cj * NCH));
            }
            cnt += __popc(m);
        }
        if (lane < 4) sWJ[p][sub][cnt + lane] = make_float2(0.0f, __int_as_float(0));
        if (lane == 0) sCnt[p][sub] = cnt;
        __syncwarp();

        // ---- Phase B: 4 neighbors x 2 batches x 16 ch per warp-iter ----
        const int cnt4 = (cnt + 3) & ~3;
        float4 acc = make_float4(0.f, 0.f, 0.f, 0.f);
        #pragma unroll 2
        for (int t = 0; t < cnt4; t += 4) {
            float2 wj = sWJ[p][sub][t + n2];
            const float4 v = *reinterpret_cast<const float4*>(xq + __float_as_int(wj.y));
            acc.x = fmaf(wj.x, v.x, acc.x);
            acc.y = fmaf(wj.x, v.y, acc.y);
            acc.z = fmaf(wj.x, v.z, acc.z);
            acc.w = fmaf(wj.x, v.w, acc.w);
        }
        #pragma unroll
        for (int o = 8; o <= 16; o <<= 1) {
            acc.x += __shfl_xor_sync(0xffffffffu, acc.x, o);
            acc.y += __shfl_xor_sync(0xffffffffu, acc.y, o);
            acc.z += __shfl_xor_sync(0xffffffffu, acc.z, o);
            acc.w += __shfl_xor_sync(0xffffffffu, acc.w, o);
        }
        if (lane < 8) sPart[p][sub][lane] = acc;
        __syncthreads();

        if (sub == 0 && lane < 8) {
            float4 s0 = sPart[p][0][lane];
            float4 s1 = sPart[p][1][lane];
            float4 s2 = sPart[p][2][lane];
            float4 s3 = sPart[p][3][lane];
            int tot = sCnt[p][0] + sCnt[p][1] + sCnt[p][2] + sCnt[p][3];
            float sc = 1.0f / (float)tot;
            float4 o;
            o.x = (s0.x + s1.x + s2.x + s3.x) * sc;
            o.y = (s0.y + s1.y + s2.y + s3.y) * sc;
            o.z = (s0.z + s1.z + s2.z + s3.z) * sc;
            o.w = (s0.w + s1.w + s2.w + s3.w) * sc;
            *reinterpret_cast<float4*>(out + bb * XSTRIDE + i * NCH + qq * 4) = o;
        }
        __syncthreads();   // protect sAp/sWJ/sPart/sCnt reuse next group
    }
}

extern "C" void kernel_launch(void* const* d_in, const int* in_sizes, int n_in,
                              void* d_out, int out_size)
{
    const float* x      = (const float*)d_in[0];
    const float* phi_w1 = (const float*)d_in[1];
    const float* phi_b1 = (const float*)d_in[2];
    const float* phi_w2 = (const float*)d_in[3];
    const float* phi_b2 = (const float*)d_in[4];
    const float* h_w1   = (const float*)d_in[5];
    const float* h_b1   = (const float*)d_in[6];
    const float* h_w2   = (const float*)d_in[7];
    const float* h_b2   = (const float*)d_in[8];
    const float* S_m    = (const float*)d_in[9];
    float* out = (float*)d_out;

    si_blocks_kernel<<<GRIDN, 256>>>(
        x, phi_w1, phi_b1, phi_w2, phi_b2,
        h_w1, h_b1, h_w2, h_b2, S_m, out);
}

// round 6
// speedup vs baseline: 1.6288x; 1.0308x over previous
#include <cuda_runtime.h>
#include <math.h>

#define GRID_H   48
#define NPTS     2304
#define NCH      16
#define IPB      2         // i's per block
#define SUBW     4         // warps per i
#define NOFF     277       // in-circle window offsets (dr^2+dc^2 <= 88)
#define MAXE     112       // per-warp compacted list capacity (96 + pad margin)
#define XSTRIDE  36864     // NPTS*NCH
#define NGRP     1152      // NPTS/IPB
#define GRIDN    592       // 148 SMs * 4 resident blocks

__device__ __forceinline__ unsigned long long pk2(float lo, float hi) {
    unsigned long long r;
    unsigned a = __float_as_uint(lo), b = __float_as_uint(hi);
    asm("mov.b64 %0, {%1, %2};" : "=l"(r) : "r"(a), "r"(b));
    return r;
}
__device__ __forceinline__ void upk2(unsigned long long v, float& lo, float& hi) {
    unsigned a, b;
    asm("mov.b64 {%0, %1}, %2;" : "=r"(a), "=r"(b) : "l"(v));
    lo = __uint_as_float(a); hi = __uint_as_float(b);
}
__device__ __forceinline__ unsigned long long ffma2(unsigned long long a,
                                                    unsigned long long b,
                                                    unsigned long long c) {
    unsigned long long d;
    asm("fma.rn.f32x2 %0, %1, %2, %3;" : "=l"(d) : "l"(a), "l"(b), "l"(c));
    return d;
}

// Phase A + spline + compaction, warp-local. NR = rounds for this warp.
template<int NR>
__device__ __forceinline__ int phase_a(
    int lane, float xi, float yi, int ri, int ci, float inv_h,
    const int* __restrict__ drv, const int* __restrict__ dcv,
    const float* __restrict__ distv, const int* __restrict__ joffv,
    const float2* __restrict__ sW2p, const float2* __restrict__ sW3p,
    const float2* __restrict__ sVp,  const float2* __restrict__ cR2,
    const float* __restrict__ sS, float b2, int ibase,
    float2* __restrict__ wjRow)
{
    const float inv47 = 1.0f / 47.0f;
    unsigned long long xs2[NR], ys2[NR], acc2[NR];
#pragma unroll
    for (int r = 0; r < NR; r++) {
        float xj = fmaf((float)drv[r], inv47, xi);
        float yj = fmaf((float)dcv[r], inv47, yi);
        xs2[r] = pk2(xj, xj);
        ys2[r] = pk2(yj, yj);
        acc2[r] = 0ULL;
    }
#pragma unroll
    for (int k2 = 0; k2 < 16; k2++) {
        float2 w2 = sW2p[k2], w3 = sW3p[k2], vv = sVp[k2], aa = cR2[k2];
        unsigned long long w2q = pk2(w2.x, w2.y);
        unsigned long long w3q = pk2(w3.x, w3.y);
        unsigned long long vq  = pk2(vv.x, vv.y);
        unsigned long long aq  = pk2(aa.x, aa.y);
#pragma unroll
        for (int r = 0; r < NR; r++) {
            unsigned long long t2 = ffma2(xs2[r], w2q, aq);
            t2 = ffma2(ys2[r], w3q, t2);
            float tl, th; upk2(t2, tl, th);
            tl = fmaxf(tl, 0.0f); th = fmaxf(th, 0.0f);
            acc2[r] = ffma2(pk2(tl, th), vq, acc2[r]);
        }
    }
    const float CKNOT = 1.0f / (1.0f / 15.0f + 1e-8f);
    int cnt = 0;
#pragma unroll
    for (int r = 0; r < NR; r++) {
        int rj = ri + drv[r];
        int cj = ci + dcv[r];
        bool ok = ((unsigned)rj < GRID_H) && ((unsigned)cj < GRID_H);
        if (NR == 3 && r == 2) ok = ok && (lane < NOFF - 256);  // partial round
        unsigned m = __ballot_sync(0xffffffffu, ok);
        if (ok) {
            float rr  = fminf(distv[r] * inv_h, 1.0f);
            int   idx = min((int)(rr * 15.0f), 14);
            float wr  = (rr - (float)idx * (1.0f / 15.0f)) * CKNOT;
            float s0  = sS[idx];
            float psi = fmaf(wr, sS[idx + 1] - s0, s0);
            float al, ah; upk2(acc2[r], al, ah);
            float w   = (al + ah + b2) * psi;
            int  pos  = cnt + __popc(m & ((1u << lane) - 1u));
            wjRow[pos] = make_float2(w, __int_as_float(ibase + joffv[r]));
        }
        cnt += __popc(m);
    }
    return cnt;
}

__global__ __launch_bounds__(256, 4)
void si_blocks_kernel(const float* __restrict__ x,
                      const float* __restrict__ phi_w1, const float* __restrict__ phi_b1,
                      const float* __restrict__ phi_w2, const float* __restrict__ phi_b2,
                      const float* __restrict__ h_w1,  const float* __restrict__ h_b1,
                      const float* __restrict__ h_w2,  const float* __restrict__ h_b2,
                      const float* __restrict__ S_m,
                      float* __restrict__ out)
{
    __shared__ float2 sW2p[16], sW3p[16], sVp[16];
    __shared__ float  sW0[32], sW1[32], sB1[32];
    __shared__ float  sHW1a[32], sHW1b[32], sHB1[32], sHW2[32];
    __shared__ float  sS[16], sDist[89];
    __shared__ float  sB2v, sHB2v;
    __shared__ int    sOff[288];                         // packed (dr+9)<<5 | (dc+9)
    __shared__ __align__(16) float sC[8][32];            // per-warp a_i row (16B-aligned!)
    __shared__ float2 sWJ[8][MAXE];                      // per-warp compacted lists
    __shared__ int    sCnt[2][8];
    __shared__ float4 sPart[2][IPB][SUBW][8];

    const int tid  = threadIdx.x;
    const int warp = tid >> 5;
    const int lane = tid & 31;
    const int p    = warp >> 2;
    const int sub  = warp & 3;
    const float inv47 = 1.0f / 47.0f;

    // ---- one-time init ----
    if (tid < 16) {
        sW2p[tid] = make_float2(phi_w1[64 + 2*tid], phi_w1[65 + 2*tid]);
        sW3p[tid] = make_float2(phi_w1[96 + 2*tid], phi_w1[97 + 2*tid]);
        sVp [tid] = make_float2(phi_w2[2*tid],      phi_w2[2*tid + 1]);
        sS  [tid] = S_m[tid];
    }
    if (tid >= 32 && tid < 64) {
        int l = tid - 32;
        sW0[l] = phi_w1[l]; sW1[l] = phi_w1[32 + l]; sB1[l] = phi_b1[l];
        sHW1a[l] = h_w1[l]; sHW1b[l] = h_w1[32 + l];
        sHB1[l] = h_b1[l];  sHW2[l] = h_w2[l];
    }
    if (tid == 16) sB2v  = phi_b2[0];
    if (tid == 17) sHB2v = h_b2[0];
    if (tid >= 64 && tid < 153) sDist[tid - 64] = sqrtf((float)(tid - 64)) * inv47;
    if (warp == 7) {   // compact in-circle offsets (deterministic order)
        int cnt = 0;
        for (int rr = 0; rr < 12; rr++) {
            int cand = lane + rr * 32;
            int q = cand / 19;
            int dr = q - 9, dc = cand - q * 19 - 9;
            bool ok = (cand < 361) && (dr * dr + dc * dc <= 88);
            unsigned m = __ballot_sync(0xffffffffu, ok);
            if (ok) sOff[cnt + __popc(m & ((1u << lane) - 1u))] = ((dr + 9) << 5) | (dc + 9);
            cnt += __popc(m);
        }
    }
    __syncthreads();

    // ---- per-warp window geometry (persistent) ----
    int   drv[3], dcv[3], joffv[3];
    float distv[3];
#pragma unroll
    for (int r = 0; r < 3; r++) {
        int slot = lane + 32 * (sub + 4 * r);
        int pk = (slot < NOFF) ? sOff[slot] : ((9 << 5) | 9);
        int dr = (pk >> 5) - 9, dc = (pk & 31) - 9;
        drv[r] = dr; dcv[r] = dc;
        distv[r] = sDist[dr * dr + dc * dc];
        joffv[r] = (dr * GRID_H + dc) * NCH;
    }

    const int n2 = lane >> 3;
    const int bb = (lane >> 2) & 1;
    const int qq = lane & 3;
    const float* xq = x + bb * XSTRIDE + qq * 4;
    const float2* cR2 = (const float2*)sC[warp];
    float2* wjRow = sWJ[warp];

    int parity = 0;
    for (int grp = blockIdx.x; grp < NGRP; grp += GRIDN) {
        const int   i  = grp * IPB + p;
        const int   ri = i / GRID_H;
        const int   ci = i - ri * GRID_H;
        const float xi = (float)ri * inv47;
        const float yi = (float)ci * inv47;

        // h_net (warp-local, redundant; no barrier)
        float hz = fmaxf(fmaf(xi, sHW1a[lane], fmaf(yi, sHW1b[lane], sHB1[lane])), 0.0f)
                   * sHW2[lane];
#pragma unroll
        for (int o = 16; o; o >>= 1) hz += __shfl_xor_sync(0xffffffffu, hz, o);
        hz += sHB2v;
        float hval  = fmaxf(hz, 0.0f) + log1pf(expf(-fabsf(hz)));
        float inv_h = 1.0f / (hval + 1e-6f);

        // a_i into own smem row (warp-local)
        sC[warp][lane] = fmaf(xi, sW0[lane], fmaf(yi, sW1[lane], sB1[lane]));
        __syncwarp();

        // Phase A + compact
        int cnt;
        if (sub == 0)
            cnt = phase_a<3>(lane, xi, yi, ri, ci, inv_h, drv, dcv, distv, joffv,
                             sW2p, sW3p, sVp, cR2, sS, sB2v, i * NCH, wjRow);
        else
            cnt = phase_a<2>(lane, xi, yi, ri, ci, inv_h, drv, dcv, distv, joffv,
                             sW2p, sW3p, sVp, cR2, sS, sB2v, i * NCH, wjRow);
        if (lane < 12) wjRow[cnt + lane] = make_float2(0.0f, __int_as_float(0));
        if (lane == 0) sCnt[parity][warp] = cnt;
        __syncwarp();

        // Phase B: 4 neighbors x 2 batches x 16 ch per warp-iter, prefetched
        const int cnt4 = (cnt + 3) & ~3;
        float4 acc = make_float4(0.f, 0.f, 0.f, 0.f);
        float2 wj = wjRow[n2];
        for (int t = 0; t < cnt4; t += 4) {
            float2 nxt = wjRow[t + 4 + n2];
            const float4 v = *reinterpret_cast<const float4*>(xq + __float_as_int(wj.y));
            acc.x = fmaf(wj.x, v.x, acc.x);
            acc.y = fmaf(wj.x, v.y, acc.y);
            acc.z = fmaf(wj.x, v.z, acc.z);
            acc.w = fmaf(wj.x, v.w, acc.w);
            wj = nxt;
        }
#pragma unroll
        for (int o = 8; o <= 16; o <<= 1) {
            acc.x += __shfl_xor_sync(0xffffffffu, acc.x, o);
            acc.y += __shfl_xor_sync(0xffffffffu, acc.y, o);
            acc.z += __shfl_xor_sync(0xffffffffu, acc.z, o);
            acc.w += __shfl_xor_sync(0xffffffffu, acc.w, o);
        }
        if (lane < 8) sPart[parity][p][sub][lane] = acc;

        // sync only the 4 warps of this i
        asm volatile("bar.sync %0, 128;" :: "r"(p + 1) : "memory");

        if (sub == 0 && lane < 8) {
            float4 s0 = sPart[parity][p][0][lane];
            float4 s1 = sPart[parity][p][1][lane];
            float4 s2 = sPart[parity][p][2][lane];
            float4 s3 = sPart[parity][p][3][lane];
            int tot = sCnt[parity][4*p] + sCnt[parity][4*p+1]
                    + sCnt[parity][4*p+2] + sCnt[parity][4*p+3];
            float sc = 1.0f / (float)tot;
            float4 o;
            o.x = (s0.x + s1.x + s2.x + s3.x) * sc;
            o.y = (s0.y + s1.y + s2.y + s3.y) * sc;
            o.z = (s0.z + s1.z + s2.z + s3.z) * sc;
            o.w = (s0.w + s1.w + s2.w + s3.w) * sc;
            *reinterpret_cast<float4*>(out + bb * XSTRIDE + i * NCH + qq * 4) = o;
        }
        parity ^= 1;
    }
}

extern "C" void kernel_launch(void* const* d_in, const int* in_sizes, int n_in,
                              void* d_out, int out_size)
{
    const float* x      = (const float*)d_in[0];
    const float* phi_w1 = (const float*)d_in[1];
    const float* phi_b1 = (const float*)d_in[2];
    const float* phi_w2 = (const float*)d_in[3];
    const float* phi_b2 = (const float*)d_in[4];
    const float* h_w1   = (const float*)d_in[5];
    const float* h_b1   = (const float*)d_in[6];
    const float* h_w2   = (const float*)d_in[7];
    const float* h_b2   = (const float*)d_in[8];
    const float* S_m    = (const float*)d_in[9];
    float* out = (float*)d_out;

    si_blocks_kernel<<<GRIDN, 256>>>(
        x, phi_w1, phi_b1, phi_w2, phi_b2,
        h_w1, h_b1, h_w2, h_b2, S_m, out);
}